// round 6
// baseline (speedup 1.0000x reference)
#include <cuda_runtime.h>
#include <cuda_bf16.h>
#include <cstdint>

#define BB 8
#define CC 512
#define NN 4096
#define CQ 80
#define NP 128   // CQ padded to 128 for bf16 MMA K

// ---------------- scratch (device globals; allocation-guard safe) ----------
__device__ __nv_bfloat16  g_vb    [(size_t)BB * CC * NN];   // 64 MB  [b][c][n]
__device__ __nv_bfloat16  g_qT    [(size_t)BB * NN * NP];   // 8 MB   [b][n][c] padded
__device__ __nv_bfloat16  g_kT    [(size_t)BB * NN * NP];   // 8 MB
__device__ __nv_bfloat16  g_xT    [(size_t)BB * NN * CC];   // 33.5 MB [b][n][c]
__device__ __nv_bfloat16  g_wv    [(size_t)CC * CC];
__device__ __nv_bfloat16  g_wqp   [(size_t)NP * CC];
__device__ __nv_bfloat16  g_wkp   [(size_t)NP * CC];

// ---------------- helpers ---------------------------------------------------
__device__ __forceinline__ uint32_t smem_u32(const void* p) {
    uint32_t a;
    asm("{ .reg .u64 t; cvta.to.shared.u64 t, %1; cvt.u32.u64 %0, t; }" : "=r"(a) : "l"(p));
    return a;
}
__device__ __forceinline__ void ldsm4(uint32_t& r0, uint32_t& r1, uint32_t& r2, uint32_t& r3,
                                      uint32_t addr) {
    asm volatile("ldmatrix.sync.aligned.m8n8.x4.shared.b16 {%0,%1,%2,%3}, [%4];"
                 : "=r"(r0), "=r"(r1), "=r"(r2), "=r"(r3) : "r"(addr));
}
__device__ __forceinline__ void mma16816(float* c, uint32_t a0, uint32_t a1, uint32_t a2,
                                         uint32_t a3, uint32_t b0, uint32_t b1) {
    asm volatile("mma.sync.aligned.m16n8k16.row.col.f32.bf16.bf16.f32 "
                 "{%0,%1,%2,%3},{%4,%5,%6,%7},{%8,%9},{%0,%1,%2,%3};"
                 : "+f"(c[0]), "+f"(c[1]), "+f"(c[2]), "+f"(c[3])
                 : "r"(a0), "r"(a1), "r"(a2), "r"(a3), "r"(b0), "r"(b1));
}
#define CP_ASYNC16(dst, src) \
    asm volatile("cp.async.cg.shared.global [%0], [%1], 16;" :: "r"(dst), "l"(src))
#define CP_COMMIT() asm volatile("cp.async.commit_group;" ::: "memory")
#define CP_WAIT1()  asm volatile("cp.async.wait_group 1;" ::: "memory")
#define CP_WAIT0()  asm volatile("cp.async.wait_group 0;" ::: "memory")

// 128B-row (64 bf16) swizzle; chunk in [0,8)
#define SW(r, c) ((uint32_t)(((r) * 128) + ((((c) ^ ((r) & 7))) * 16)))
// 256B-row (128 bf16) swizzle; chunk in [0,16)
#define SW2(r, c) ((uint32_t)(((r) * 256) + ((((c) ^ ((r) & 7))) * 16)))

// ---------------------------------------------------------------------------
// 128x128 bf16 GEMM body (projections). C += A[128,K] * B[128,K]^T
// ---------------------------------------------------------------------------
template <int NK>
__device__ __forceinline__ void gemm128x128(uint32_t sb, const uint4* __restrict__ Ag,
                                            const uint4* __restrict__ Bg, int aStride,
                                            int bStride, int m0, int n0,
                                            float (&acc)[4][4][4]) {
    const int tid = threadIdx.x;
    const int lane = tid & 31, wid = tid >> 5;
    const int wm = wid >> 2, wn = wid & 3;
    const int lr = tid >> 3, lc = tid & 7;

    int a_r[4], b_r[2];
#pragma unroll
    for (int mt = 0; mt < 4; mt++) a_r[mt] = wm * 64 + mt * 16 + ((lane >> 3) & 1) * 8 + (lane & 7);
#pragma unroll
    for (int p = 0; p < 2; p++) b_r[p] = wn * 32 + p * 16 + ((lane >> 4) & 1) * 8 + (lane & 7);
    const int a_kc = (lane >> 4) & 1;
    const int b_kc = (lane >> 3) & 1;

    {
        uint32_t dA = sb, dB = sb + 16384;
#pragma unroll
        for (int p = 0; p < 4; p++) {
            int r = p * 32 + lr;
            CP_ASYNC16(dA + SW(r, lc), (const void*)(Ag + (size_t)(m0 + r) * aStride + lc));
            CP_ASYNC16(dB + SW(r, lc), (const void*)(Bg + (size_t)(n0 + r) * bStride + lc));
        }
        CP_COMMIT();
    }

#pragma unroll 1
    for (int t = 0; t < NK; t++) {
        if (t + 1 < NK) {
            uint32_t dA = sb + ((t + 1) & 1) * 32768, dB = dA + 16384;
#pragma unroll
            for (int p = 0; p < 4; p++) {
                int r = p * 32 + lr;
                CP_ASYNC16(dA + SW(r, lc),
                           (const void*)(Ag + (size_t)(m0 + r) * aStride + (t + 1) * 8 + lc));
                CP_ASYNC16(dB + SW(r, lc),
                           (const void*)(Bg + (size_t)(n0 + r) * bStride + (t + 1) * 8 + lc));
            }
            CP_COMMIT();
            CP_WAIT1();
        } else {
            CP_WAIT0();
        }
        __syncthreads();

        const uint32_t Asb = sb + (t & 1) * 32768;
        const uint32_t Bsb = Asb + 16384;
#pragma unroll
        for (int ks = 0; ks < 4; ks++) {
            uint32_t aF[4][4], bF[2][4];
#pragma unroll
            for (int mt = 0; mt < 4; mt++)
                ldsm4(aF[mt][0], aF[mt][1], aF[mt][2], aF[mt][3],
                      Asb + SW(a_r[mt], ks * 2 + a_kc));
#pragma unroll
            for (int p = 0; p < 2; p++)
                ldsm4(bF[p][0], bF[p][1], bF[p][2], bF[p][3],
                      Bsb + SW(b_r[p], ks * 2 + b_kc));
#pragma unroll
            for (int mt = 0; mt < 4; mt++) {
                mma16816(acc[mt][0], aF[mt][0], aF[mt][1], aF[mt][2], aF[mt][3], bF[0][0], bF[0][1]);
                mma16816(acc[mt][1], aF[mt][0], aF[mt][1], aF[mt][2], aF[mt][3], bF[0][2], bF[0][3]);
                mma16816(acc[mt][2], aF[mt][0], aF[mt][1], aF[mt][2], aF[mt][3], bF[1][0], bF[1][1]);
                mma16816(acc[mt][3], aF[mt][0], aF[mt][1], aF[mt][2], aF[mt][3], bF[1][2], bF[1][3]);
            }
        }
        __syncthreads();
    }
}

// ---------------------------------------------------------------------------
// convert_w / transpose_x / proj_qk / proj_v (unchanged, working)
// ---------------------------------------------------------------------------
__global__ __launch_bounds__(256)
void convert_w_kernel(const float* __restrict__ Wv, const float* __restrict__ Wq,
                      const float* __restrict__ Wk)
{
    int idx = blockIdx.x * 256 + threadIdx.x;
    if (idx < CC * CC) {
        g_wv[idx] = __float2bfloat16(Wv[idx]);
    } else if (idx < CC * CC + NP * CC) {
        int i = idx - CC * CC;
        int row = i >> 9, col = i & 511;
        g_wqp[i] = __float2bfloat16(row < CQ ? Wq[row * CC + col] : 0.f);
    } else {
        int i = idx - CC * CC - NP * CC;
        int row = i >> 9, col = i & 511;
        g_wkp[i] = __float2bfloat16(row < CQ ? Wk[row * CC + col] : 0.f);
    }
}

__global__ __launch_bounds__(256)
void transpose_x_kernel(const float* __restrict__ x)
{
    __shared__ __nv_bfloat16 st[128][136];
    const int b  = blockIdx.z;
    const int c0 = blockIdx.x * 128;
    const int n0 = blockIdx.y * 128;
    const int tid = threadIdx.x;

    const float* xb = x + (size_t)b * CC * NN;
#pragma unroll
    for (int k = 0; k < 8; k++) {
        int row = k * 16 + (tid >> 4);
        int col = (tid & 15) * 8;
        const float* p = xb + (size_t)(c0 + row) * NN + n0 + col;
        float4 v0 = *(const float4*)p;
        float4 v1 = *(const float4*)(p + 4);
        st[col + 0][row] = __float2bfloat16(v0.x);
        st[col + 1][row] = __float2bfloat16(v0.y);
        st[col + 2][row] = __float2bfloat16(v0.z);
        st[col + 3][row] = __float2bfloat16(v0.w);
        st[col + 4][row] = __float2bfloat16(v1.x);
        st[col + 5][row] = __float2bfloat16(v1.y);
        st[col + 6][row] = __float2bfloat16(v1.z);
        st[col + 7][row] = __float2bfloat16(v1.w);
    }
    __syncthreads();

    uint4* xT = (uint4*)(g_xT + (size_t)b * NN * CC);
#pragma unroll
    for (int k = 0; k < 8; k++) {
        int idx = k * 256 + tid;
        int r = idx >> 4, j = idx & 15;
        uint4 val = *(uint4*)&st[r][j * 8];
        xT[(size_t)(n0 + r) * (CC / 8) + (c0 >> 3) + j] = val;
    }
}

__global__ __launch_bounds__(256)
void proj_qk_kernel(const float* __restrict__ scale, const float* __restrict__ bias,
                    int which)
{
    extern __shared__ __align__(1024) char smem[];
    const uint32_t sb = smem_u32(smem);
    const int tid = threadIdx.x;
    const int lane = tid & 31, wid = tid >> 5;
    const int wm = wid >> 2, wn = wid & 3;
    const int bz = blockIdx.z, n0 = blockIdx.x * 128;

    const uint4* Ag = (const uint4*)(g_xT + (size_t)bz * NN * CC);
    const uint4* Bg = (const uint4*)(which ? g_wkp : g_wqp);

    float acc[4][4][4];
#pragma unroll
    for (int i = 0; i < 4; i++)
#pragma unroll
        for (int j = 0; j < 4; j++)
#pragma unroll
            for (int k = 0; k < 4; k++) acc[i][j][k] = 0.f;

    gemm128x128<8>(sb, Ag, Bg, CC / 8, CC / 8, n0, 0, acc);

    __nv_bfloat16* qT = (which ? g_kT : g_qT) + (size_t)bz * NN * NP;
    const int g = lane >> 2, tg = lane & 3;
#pragma unroll
    for (int mt = 0; mt < 4; mt++) {
#pragma unroll
        for (int half = 0; half < 2; half++) {
            int row = n0 + wm * 64 + mt * 16 + g + half * 8;
#pragma unroll
            for (int nt = 0; nt < 4; nt++) {
                int c = wn * 32 + nt * 8 + tg * 2;
                float r0 = 0.f, r1 = 0.f;
                if (c < CQ) {
                    r0 = fmaf(acc[mt][nt][half * 2 + 0], scale[c], bias[c]);
                    r1 = fmaf(acc[mt][nt][half * 2 + 1], scale[c + 1], bias[c + 1]);
                    r0 = r0 > 0.f ? r0 : 0.f;
                    r1 = r1 > 0.f ? r1 : 0.f;
                }
                __nv_bfloat162 pk;
                pk.x = __float2bfloat16(r0);
                pk.y = __float2bfloat16(r1);
                *(__nv_bfloat162*)&qT[(size_t)row * NP + c] = pk;
            }
        }
    }
}

__global__ __launch_bounds__(256)
void proj_v_kernel(const float* __restrict__ scale, const float* __restrict__ bias)
{
    extern __shared__ __align__(1024) char smem[];
    const uint32_t sb = smem_u32(smem);
    const int tid = threadIdx.x;
    const int lane = tid & 31, wid = tid >> 5;
    const int wm = wid >> 2, wn = wid & 3;
    const int bz = blockIdx.z, c0 = blockIdx.x * 128, n0 = blockIdx.y * 128;

    const uint4* Ag = (const uint4*)g_wv;
    const uint4* Bg = (const uint4*)(g_xT + (size_t)bz * NN * CC);

    float acc[4][4][4];
#pragma unroll
    for (int i = 0; i < 4; i++)
#pragma unroll
        for (int j = 0; j < 4; j++)
#pragma unroll
            for (int k = 0; k < 4; k++) acc[i][j][k] = 0.f;

    gemm128x128<8>(sb, Ag, Bg, CC / 8, CC / 8, c0, n0, acc);

    __nv_bfloat16* Yb = g_vb + (size_t)bz * CC * NN;
    const int g = lane >> 2, tg = lane & 3;
#pragma unroll
    for (int mt = 0; mt < 4; mt++) {
#pragma unroll
        for (int half = 0; half < 2; half++) {
            int c = c0 + wm * 64 + mt * 16 + g + half * 8;
            float s = scale[c], bi = bias[c];
#pragma unroll
            for (int nt = 0; nt < 4; nt++) {
                int n = n0 + wn * 32 + nt * 8 + tg * 2;
                float r0 = fmaf(acc[mt][nt][half * 2 + 0], s, bi);
                float r1 = fmaf(acc[mt][nt][half * 2 + 1], s, bi);
                __nv_bfloat162 pk;
                pk.x = __float2bfloat16(r0 > 0.f ? r0 : 0.f);
                pk.y = __float2bfloat16(r1 > 0.f ? r1 : 0.f);
                *(__nv_bfloat162*)&Yb[(size_t)c * NN + n] = pk;
            }
        }
    }
}

// ---------------------------------------------------------------------------
// FLASH kernel: per CTA (i-tile 64, c-half 256, batch b):
//   loop j in 64-chunks: S = q·k^T (online softmax) -> P (bf16, smem) -> O += P·V^T
//   epilogue: out = gamma * O/l + x  (coalesced via smem stage)
// Warps: wm = wid>>1 (4 x 16 i-rows), wn = wid&1 (2 x 128 c).
// smem: Q 16K | K dbl 2x16K | V dbl 2x32K | P 8K | red 1K   (~121 KB)
// ---------------------------------------------------------------------------
#define FQ  0
#define FK  16384
#define FV  49152
#define FP  114688
#define FMX 122880
#define FSMU 123392
#define FOS 49152         // epilogue O stage (64 KB) reuses V area
#define FSMEM 123904

__global__ void __launch_bounds__(256, 1)
flash_kernel(const float* __restrict__ gamma, const float* __restrict__ x,
             float* __restrict__ out)
{
    extern __shared__ __align__(1024) char smem[];
    const uint32_t sb = smem_u32(smem);
    const int tid = threadIdx.x;
    const int lane = tid & 31, wid = tid >> 5;
    const int wm = wid >> 1, wn = wid & 1;
    const int g = lane >> 2, tg = lane & 3;
    const int bz = blockIdx.z, i0 = blockIdx.x * 64, ch = blockIdx.y;

    const char* qg = (const char*)(g_qT + ((size_t)bz * NN + i0) * NP);
    const char* kg = (const char*)(g_kT + (size_t)bz * NN * NP);
    const char* vg = (const char*)(g_vb + ((size_t)bz * CC + (size_t)ch * 256) * NN);

    float* pmax = (float*)(smem + FMX);    // [64][2]
    float* psum = (float*)(smem + FSMU);   // [64][2]

    // ---- prologue: Q (group 0), K0+V0 (group 1)
    {
#pragma unroll
        for (int p = 0; p < 4; p++) {
            int idx = p * 256 + tid;
            int r = idx >> 4, c16 = idx & 15;
            CP_ASYNC16(sb + FQ + SW2(r, c16), qg + (size_t)r * 256 + c16 * 16);
        }
        CP_COMMIT();
#pragma unroll
        for (int p = 0; p < 4; p++) {
            int idx = p * 256 + tid;
            int r = idx >> 4, c16 = idx & 15;
            CP_ASYNC16(sb + FK + SW2(r, c16), kg + (size_t)r * 256 + c16 * 16);
        }
#pragma unroll
        for (int p = 0; p < 8; p++) {
            int idx = p * 256 + tid;
            int r = idx >> 3, c8 = idx & 7;
            CP_ASYNC16(sb + FV + SW(r, c8), vg + (size_t)r * 8192 + c8 * 16);
        }
        CP_COMMIT();
    }
    CP_WAIT1();          // Q ready
    __syncthreads();

    // preload q fragments (persist in registers): rows wm*16..+15, K=128
    const int a_row = wm * 16 + ((lane >> 3) & 1) * 8 + (lane & 7);
    const int a_kc = (lane >> 4) & 1;
    const int b_kc = (lane >> 3) & 1;
    uint32_t qf[8][4];
#pragma unroll
    for (int ks = 0; ks < 8; ks++)
        ldsm4(qf[ks][0], qf[ks][1], qf[ks][2], qf[ks][3], sb + FQ + SW2(a_row, ks * 2 + a_kc));

    int kb_r[2];
#pragma unroll
    for (int p = 0; p < 2; p++) kb_r[p] = wn * 32 + p * 16 + ((lane >> 4) & 1) * 8 + (lane & 7);
    int vb_r[8];
#pragma unroll
    for (int ng = 0; ng < 8; ng++)
        vb_r[ng] = wn * 128 + ng * 16 + ((lane >> 4) & 1) * 8 + (lane & 7);

    float oacc[16][4];
#pragma unroll
    for (int i = 0; i < 16; i++)
#pragma unroll
        for (int k = 0; k < 4; k++) oacc[i][k] = 0.f;
    float m_run[2] = {-1e30f, -1e30f};
    float l_run[2] = {0.f, 0.f};

#pragma unroll 1
    for (int jc = 0; jc < 64; jc++) {
        // prefetch next chunk
        if (jc + 1 < 64) {
            const uint32_t Kd = sb + FK + ((jc + 1) & 1) * 16384;
            const char* ksrc = kg + (size_t)(jc + 1) * 64 * 256;
#pragma unroll
            for (int p = 0; p < 4; p++) {
                int idx = p * 256 + tid;
                int r = idx >> 4, c16 = idx & 15;
                CP_ASYNC16(Kd + SW2(r, c16), ksrc + (size_t)r * 256 + c16 * 16);
            }
            const uint32_t Vd = sb + FV + ((jc + 1) & 1) * 32768;
            const char* vsrc = vg + (size_t)(jc + 1) * 128;
#pragma unroll
            for (int p = 0; p < 8; p++) {
                int idx = p * 256 + tid;
                int r = idx >> 3, c8 = idx & 7;
                CP_ASYNC16(Vd + SW(r, c8), vsrc + (size_t)r * 8192 + c8 * 16);
            }
            CP_COMMIT();
            CP_WAIT1();
        } else {
            CP_WAIT0();
        }
        __syncthreads();

        const uint32_t Kb = sb + FK + (jc & 1) * 16384;
        const uint32_t Vb = sb + FV + (jc & 1) * 32768;

        // ---- S = q · k^T  (16 i x 64 j per warp-pair; wn splits j 2x32)
        float sacc[4][4];
#pragma unroll
        for (int nt = 0; nt < 4; nt++)
#pragma unroll
            for (int k = 0; k < 4; k++) sacc[nt][k] = 0.f;
#pragma unroll
        for (int ks = 0; ks < 8; ks++) {
            uint32_t bF[2][4];
#pragma unroll
            for (int p = 0; p < 2; p++)
                ldsm4(bF[p][0], bF[p][1], bF[p][2], bF[p][3],
                      Kb + SW2(kb_r[p], ks * 2 + b_kc));
            mma16816(sacc[0], qf[ks][0], qf[ks][1], qf[ks][2], qf[ks][3], bF[0][0], bF[0][1]);
            mma16816(sacc[1], qf[ks][0], qf[ks][1], qf[ks][2], qf[ks][3], bF[0][2], bF[0][3]);
            mma16816(sacc[2], qf[ks][0], qf[ks][1], qf[ks][2], qf[ks][3], bF[1][0], bF[1][1]);
            mma16816(sacc[3], qf[ks][0], qf[ks][1], qf[ks][2], qf[ks][3], bF[1][2], bF[1][3]);
        }

        // ---- online softmax: partial max exchange across wn
        float pm0 = -1e30f, pm1 = -1e30f;
#pragma unroll
        for (int nt = 0; nt < 4; nt++) {
            pm0 = fmaxf(pm0, fmaxf(sacc[nt][0], sacc[nt][1]));
            pm1 = fmaxf(pm1, fmaxf(sacc[nt][2], sacc[nt][3]));
        }
        pm0 = fmaxf(pm0, __shfl_xor_sync(0xffffffffu, pm0, 1));
        pm0 = fmaxf(pm0, __shfl_xor_sync(0xffffffffu, pm0, 2));
        pm1 = fmaxf(pm1, __shfl_xor_sync(0xffffffffu, pm1, 1));
        pm1 = fmaxf(pm1, __shfl_xor_sync(0xffffffffu, pm1, 2));
        if (tg == 0) {
            pmax[(wm * 16 + g) * 2 + wn] = pm0;
            pmax[(wm * 16 + g + 8) * 2 + wn] = pm1;
        }
        __syncthreads();

        float mnew[2], scl[2];
#pragma unroll
        for (int h = 0; h < 2; h++) {
            int row = wm * 16 + g + h * 8;
            float mc = fmaxf(pmax[row * 2], pmax[row * 2 + 1]);
            mnew[h] = fmaxf(m_run[h], mc);
            scl[h] = __expf(m_run[h] - mnew[h]);
            m_run[h] = mnew[h];
        }
        // rescale O acc only when some lane saw a new max
        if (__ballot_sync(0xffffffffu, (scl[0] != 1.f) | (scl[1] != 1.f))) {
#pragma unroll
            for (int nt = 0; nt < 16; nt++) {
                oacc[nt][0] *= scl[0]; oacc[nt][1] *= scl[0];
                oacc[nt][2] *= scl[1]; oacc[nt][3] *= scl[1];
            }
        }

        // ---- P = exp(S - m) -> smem (bf16), partial row sums
        float ps0 = 0.f, ps1 = 0.f;
#pragma unroll
        for (int nt = 0; nt < 4; nt++) {
            float p00 = __expf(sacc[nt][0] - mnew[0]);
            float p01 = __expf(sacc[nt][1] - mnew[0]);
            float p10 = __expf(sacc[nt][2] - mnew[1]);
            float p11 = __expf(sacc[nt][3] - mnew[1]);
            ps0 += p00 + p01;
            ps1 += p10 + p11;
            int jl = wn * 32 + nt * 8 + tg * 2;
            uint32_t coff = (uint32_t)(((jl >> 3) ^ ((wm * 16 + g) & 7)) * 16) + ((jl * 2) & 15);
            __nv_bfloat162 pk0 = __float22bfloat162_rn(make_float2(p00, p01));
            uint32_t addr0 = sb + FP + (wm * 16 + g) * 128 + coff;
            asm volatile("st.shared.b32 [%0], %1;" :: "r"(addr0), "r"(*(uint32_t*)&pk0) : "memory");
            uint32_t coff1 = (uint32_t)(((jl >> 3) ^ ((wm * 16 + g + 8) & 7)) * 16) + ((jl * 2) & 15);
            __nv_bfloat162 pk1 = __float22bfloat162_rn(make_float2(p10, p11));
            uint32_t addr1 = sb + FP + (wm * 16 + g + 8) * 128 + coff1;
            asm volatile("st.shared.b32 [%0], %1;" :: "r"(addr1), "r"(*(uint32_t*)&pk1) : "memory");
        }
        ps0 += __shfl_xor_sync(0xffffffffu, ps0, 1);
        ps0 += __shfl_xor_sync(0xffffffffu, ps0, 2);
        ps1 += __shfl_xor_sync(0xffffffffu, ps1, 1);
        ps1 += __shfl_xor_sync(0xffffffffu, ps1, 2);
        if (tg == 0) {
            psum[(wm * 16 + g) * 2 + wn] = ps0;
            psum[(wm * 16 + g + 8) * 2 + wn] = ps1;
        }
        __syncthreads();
#pragma unroll
        for (int h = 0; h < 2; h++) {
            int row = wm * 16 + g + h * 8;
            float lc = psum[row * 2] + psum[row * 2 + 1];
            l_run[h] = l_run[h] * scl[h] + lc;
        }

        // ---- O += P · V^T
#pragma unroll
        for (int kk = 0; kk < 4; kk++) {
            uint32_t aF[4];
            ldsm4(aF[0], aF[1], aF[2], aF[3], sb + FP + SW(a_row, kk * 2 + a_kc));
#pragma unroll
            for (int ng = 0; ng < 8; ng++) {
                uint32_t bV[4];
                ldsm4(bV[0], bV[1], bV[2], bV[3], Vb + SW(vb_r[ng], kk * 2 + b_kc));
                mma16816(oacc[ng * 2 + 0], aF[0], aF[1], aF[2], aF[3], bV[0], bV[1]);
                mma16816(oacc[ng * 2 + 1], aF[0], aF[1], aF[2], aF[3], bV[2], bV[3]);
            }
        }
        __syncthreads();   // release buffers for next prefetch
    }

    // ---- epilogue: O/l staged to smem (reuse V area), fused coalesced write
    const float li0 = 1.f / l_run[0];
    const float li1 = 1.f / l_run[1];
#pragma unroll
    for (int nt = 0; nt < 16; nt++) {
        int c_local = wn * 128 + nt * 8 + tg * 2;
        int r0 = wm * 16 + g, r1 = r0 + 8;
        *(float*)(smem + FOS + (size_t)c_local * 256 + r0 * 4)       = oacc[nt][0] * li0;
        *(float*)(smem + FOS + (size_t)(c_local + 1) * 256 + r0 * 4) = oacc[nt][1] * li0;
        *(float*)(smem + FOS + (size_t)c_local * 256 + r1 * 4)       = oacc[nt][2] * li1;
        *(float*)(smem + FOS + (size_t)(c_local + 1) * 256 + r1 * 4) = oacc[nt][3] * li1;
    }
    __syncthreads();

#pragma unroll
    for (int p = 0; p < 16; p++) {
        int idx = p * 256 + tid;
        int r = idx >> 4, q4 = idx & 15;
        int c = ch * 256 + r;
        int ii = i0 + q4 * 4;
        float4 o4 = *(float4*)(smem + FOS + (size_t)r * 256 + q4 * 16);
        size_t gi = (size_t)c * NN + ii;
        size_t bi = (size_t)bz * CC * NN + gi;
        float4 g4 = *(const float4*)(gamma + gi);
        float4 x4 = *(const float4*)(x + bi);
        float4 w;
        w.x = fmaf(g4.x, o4.x, x4.x);
        w.y = fmaf(g4.y, o4.y, x4.y);
        w.z = fmaf(g4.z, o4.z, x4.z);
        w.w = fmaf(g4.w, o4.w, x4.w);
        *(float4*)(out + bi) = w;
    }
}

// ---------------------------------------------------------------------------
extern "C" void kernel_launch(void* const* d_in, const int* in_sizes, int n_in,
                              void* d_out, int out_size)
{
    const float* x     = (const float*)d_in[0];
    const float* Wq    = (const float*)d_in[1];
    const float* Wk    = (const float*)d_in[2];
    const float* Wv    = (const float*)d_in[3];
    const float* sq    = (const float*)d_in[4];
    const float* bq    = (const float*)d_in[5];
    const float* sk    = (const float*)d_in[6];
    const float* bk    = (const float*)d_in[7];
    const float* sv    = (const float*)d_in[8];
    const float* bv    = (const float*)d_in[9];
    const float* gamma = (const float*)d_in[10];
    float* out = (float*)d_out;

    const int DSMEM = 65536;
    cudaFuncSetAttribute(proj_qk_kernel, cudaFuncAttributeMaxDynamicSharedMemorySize, DSMEM);
    cudaFuncSetAttribute(proj_v_kernel,  cudaFuncAttributeMaxDynamicSharedMemorySize, DSMEM);
    cudaFuncSetAttribute(flash_kernel,   cudaFuncAttributeMaxDynamicSharedMemorySize, FSMEM);

    dim3 blk(256);

    convert_w_kernel<<<(CC * CC + 2 * NP * CC) / 256, blk>>>(Wv, Wq, Wk);
    transpose_x_kernel<<<dim3(CC / 128, NN / 128, BB), blk>>>(x);

    proj_qk_kernel<<<dim3(NN / 128, 1, BB), blk, DSMEM>>>(sq, bq, 0);
    proj_qk_kernel<<<dim3(NN / 128, 1, BB), blk, DSMEM>>>(sk, bk, 1);
    proj_v_kernel<<<dim3(CC / 128, NN / 128, BB), blk, DSMEM>>>(sv, bv);

    flash_kernel<<<dim3(NN / 64, 2, BB), blk, FSMEM>>>(gamma, x, out);
}

// round 7
// speedup vs baseline: 1.2392x; 1.2392x over previous
#include <cuda_runtime.h>
#include <cuda_bf16.h>
#include <cstdint>

#define BB 8
#define CC 512
#define NN 4096
#define CQ 80
#define NP 128   // CQ padded to 128 for bf16 MMA K

// ---------------- scratch (device globals; allocation-guard safe) ----------
__device__ __nv_bfloat16  g_attnb [(size_t)BB * NN * NN];   // 256 MB bf16 (unnormalized P)
__device__ float          g_linv  [(size_t)BB * NN];        // 1/rowsum
__device__ __nv_bfloat16  g_vb    [(size_t)BB * CC * NN];   // 64 MB  [b][c][n]
__device__ __nv_bfloat16  g_qT    [(size_t)BB * NN * NP];   // 8 MB   [b][n][c] padded
__device__ __nv_bfloat16  g_kT    [(size_t)BB * NN * NP];   // 8 MB
__device__ __nv_bfloat16  g_xT    [(size_t)BB * NN * CC];   // 33.5 MB [b][n][c]
__device__ __nv_bfloat16  g_wv    [(size_t)CC * CC];
__device__ __nv_bfloat16  g_wqp   [(size_t)NP * CC];
__device__ __nv_bfloat16  g_wkp   [(size_t)NP * CC];

// ---------------- helpers ---------------------------------------------------
__device__ __forceinline__ uint32_t smem_u32(const void* p) {
    uint32_t a;
    asm("{ .reg .u64 t; cvta.to.shared.u64 t, %1; cvt.u32.u64 %0, t; }" : "=r"(a) : "l"(p));
    return a;
}
__device__ __forceinline__ void ldsm4(uint32_t& r0, uint32_t& r1, uint32_t& r2, uint32_t& r3,
                                      uint32_t addr) {
    asm volatile("ldmatrix.sync.aligned.m8n8.x4.shared.b16 {%0,%1,%2,%3}, [%4];"
                 : "=r"(r0), "=r"(r1), "=r"(r2), "=r"(r3) : "r"(addr));
}
__device__ __forceinline__ void mma16816(float* c, uint32_t a0, uint32_t a1, uint32_t a2,
                                         uint32_t a3, uint32_t b0, uint32_t b1) {
    asm volatile("mma.sync.aligned.m16n8k16.row.col.f32.bf16.bf16.f32 "
                 "{%0,%1,%2,%3},{%4,%5,%6,%7},{%8,%9},{%0,%1,%2,%3};"
                 : "+f"(c[0]), "+f"(c[1]), "+f"(c[2]), "+f"(c[3])
                 : "r"(a0), "r"(a1), "r"(a2), "r"(a3), "r"(b0), "r"(b1));
}
#define CP_ASYNC16(dst, src) \
    asm volatile("cp.async.cg.shared.global [%0], [%1], 16;" :: "r"(dst), "l"(src))
#define CP_COMMIT() asm volatile("cp.async.commit_group;" ::: "memory")
#define CP_WAIT1()  asm volatile("cp.async.wait_group 1;" ::: "memory")
#define CP_WAIT0()  asm volatile("cp.async.wait_group 0;" ::: "memory")

// 128B-row (64 bf16) swizzle; chunk in [0,8)
#define SW(r, c) ((uint32_t)(((r) * 128) + ((((c) ^ ((r) & 7))) * 16)))
// 256B-row (128 bf16) swizzle; chunk in [0,16)
#define SW2(r, c) ((uint32_t)(((r) * 256) + ((((c) ^ ((r) & 7))) * 16)))

// ---------------------------------------------------------------------------
// 128x128 bf16 GEMM body.  C += A[128,K] * B[128,K]^T
// ---------------------------------------------------------------------------
template <int NK>
__device__ __forceinline__ void gemm128x128(uint32_t sb, const uint4* __restrict__ Ag,
                                            const uint4* __restrict__ Bg, int aStride,
                                            int bStride, int m0, int n0,
                                            float (&acc)[4][4][4]) {
    const int tid = threadIdx.x;
    const int lane = tid & 31, wid = tid >> 5;
    const int wm = wid >> 2, wn = wid & 3;
    const int lr = tid >> 3, lc = tid & 7;

    int a_r[4], b_r[2];
#pragma unroll
    for (int mt = 0; mt < 4; mt++) a_r[mt] = wm * 64 + mt * 16 + ((lane >> 3) & 1) * 8 + (lane & 7);
#pragma unroll
    for (int p = 0; p < 2; p++) b_r[p] = wn * 32 + p * 16 + ((lane >> 4) & 1) * 8 + (lane & 7);
    const int a_kc = (lane >> 4) & 1;
    const int b_kc = (lane >> 3) & 1;

    {
        uint32_t dA = sb, dB = sb + 16384;
#pragma unroll
        for (int p = 0; p < 4; p++) {
            int r = p * 32 + lr;
            CP_ASYNC16(dA + SW(r, lc), (const void*)(Ag + (size_t)(m0 + r) * aStride + lc));
            CP_ASYNC16(dB + SW(r, lc), (const void*)(Bg + (size_t)(n0 + r) * bStride + lc));
        }
        CP_COMMIT();
    }

#pragma unroll 1
    for (int t = 0; t < NK; t++) {
        if (t + 1 < NK) {
            uint32_t dA = sb + ((t + 1) & 1) * 32768, dB = dA + 16384;
#pragma unroll
            for (int p = 0; p < 4; p++) {
                int r = p * 32 + lr;
                CP_ASYNC16(dA + SW(r, lc),
                           (const void*)(Ag + (size_t)(m0 + r) * aStride + (t + 1) * 8 + lc));
                CP_ASYNC16(dB + SW(r, lc),
                           (const void*)(Bg + (size_t)(n0 + r) * bStride + (t + 1) * 8 + lc));
            }
            CP_COMMIT();
            CP_WAIT1();
        } else {
            CP_WAIT0();
        }
        __syncthreads();

        const uint32_t Asb = sb + (t & 1) * 32768;
        const uint32_t Bsb = Asb + 16384;
#pragma unroll
        for (int ks = 0; ks < 4; ks++) {
            uint32_t aF[4][4], bF[2][4];
#pragma unroll
            for (int mt = 0; mt < 4; mt++)
                ldsm4(aF[mt][0], aF[mt][1], aF[mt][2], aF[mt][3],
                      Asb + SW(a_r[mt], ks * 2 + a_kc));
#pragma unroll
            for (int p = 0; p < 2; p++)
                ldsm4(bF[p][0], bF[p][1], bF[p][2], bF[p][3],
                      Bsb + SW(b_r[p], ks * 2 + b_kc));
#pragma unroll
            for (int mt = 0; mt < 4; mt++) {
                mma16816(acc[mt][0], aF[mt][0], aF[mt][1], aF[mt][2], aF[mt][3], bF[0][0], bF[0][1]);
                mma16816(acc[mt][1], aF[mt][0], aF[mt][1], aF[mt][2], aF[mt][3], bF[0][2], bF[0][3]);
                mma16816(acc[mt][2], aF[mt][0], aF[mt][1], aF[mt][2], aF[mt][3], bF[1][0], bF[1][1]);
                mma16816(acc[mt][3], aF[mt][0], aF[mt][1], aF[mt][2], aF[mt][3], bF[1][2], bF[1][3]);
            }
        }
        __syncthreads();
    }
}

// ---------------------------------------------------------------------------
// convert_w / transpose_x / proj_qk / proj_v (unchanged, working)
// ---------------------------------------------------------------------------
__global__ __launch_bounds__(256)
void convert_w_kernel(const float* __restrict__ Wv, const float* __restrict__ Wq,
                      const float* __restrict__ Wk)
{
    int idx = blockIdx.x * 256 + threadIdx.x;
    if (idx < CC * CC) {
        g_wv[idx] = __float2bfloat16(Wv[idx]);
    } else if (idx < CC * CC + NP * CC) {
        int i = idx - CC * CC;
        int row = i >> 9, col = i & 511;
        g_wqp[i] = __float2bfloat16(row < CQ ? Wq[row * CC + col] : 0.f);
    } else {
        int i = idx - CC * CC - NP * CC;
        int row = i >> 9, col = i & 511;
        g_wkp[i] = __float2bfloat16(row < CQ ? Wk[row * CC + col] : 0.f);
    }
}

__global__ __launch_bounds__(256)
void transpose_x_kernel(const float* __restrict__ x)
{
    __shared__ __nv_bfloat16 st[128][136];
    const int b  = blockIdx.z;
    const int c0 = blockIdx.x * 128;
    const int n0 = blockIdx.y * 128;
    const int tid = threadIdx.x;

    const float* xb = x + (size_t)b * CC * NN;
#pragma unroll
    for (int k = 0; k < 8; k++) {
        int row = k * 16 + (tid >> 4);
        int col = (tid & 15) * 8;
        const float* p = xb + (size_t)(c0 + row) * NN + n0 + col;
        float4 v0 = *(const float4*)p;
        float4 v1 = *(const float4*)(p + 4);
        st[col + 0][row] = __float2bfloat16(v0.x);
        st[col + 1][row] = __float2bfloat16(v0.y);
        st[col + 2][row] = __float2bfloat16(v0.z);
        st[col + 3][row] = __float2bfloat16(v0.w);
        st[col + 4][row] = __float2bfloat16(v1.x);
        st[col + 5][row] = __float2bfloat16(v1.y);
        st[col + 6][row] = __float2bfloat16(v1.z);
        st[col + 7][row] = __float2bfloat16(v1.w);
    }
    __syncthreads();

    uint4* xT = (uint4*)(g_xT + (size_t)b * NN * CC);
#pragma unroll
    for (int k = 0; k < 8; k++) {
        int idx = k * 256 + tid;
        int r = idx >> 4, j = idx & 15;
        uint4 val = *(uint4*)&st[r][j * 8];
        xT[(size_t)(n0 + r) * (CC / 8) + (c0 >> 3) + j] = val;
    }
}

__global__ __launch_bounds__(256)
void proj_qk_kernel(const float* __restrict__ scale, const float* __restrict__ bias,
                    int which)
{
    extern __shared__ __align__(1024) char smem[];
    const uint32_t sb = smem_u32(smem);
    const int tid = threadIdx.x;
    const int lane = tid & 31, wid = tid >> 5;
    const int wm = wid >> 2, wn = wid & 3;
    const int bz = blockIdx.z, n0 = blockIdx.x * 128;

    const uint4* Ag = (const uint4*)(g_xT + (size_t)bz * NN * CC);
    const uint4* Bg = (const uint4*)(which ? g_wkp : g_wqp);

    float acc[4][4][4];
#pragma unroll
    for (int i = 0; i < 4; i++)
#pragma unroll
        for (int j = 0; j < 4; j++)
#pragma unroll
            for (int k = 0; k < 4; k++) acc[i][j][k] = 0.f;

    gemm128x128<8>(sb, Ag, Bg, CC / 8, CC / 8, n0, 0, acc);

    __nv_bfloat16* qT = (which ? g_kT : g_qT) + (size_t)bz * NN * NP;
    const int g = lane >> 2, tg = lane & 3;
#pragma unroll
    for (int mt = 0; mt < 4; mt++) {
#pragma unroll
        for (int half = 0; half < 2; half++) {
            int row = n0 + wm * 64 + mt * 16 + g + half * 8;
#pragma unroll
            for (int nt = 0; nt < 4; nt++) {
                int c = wn * 32 + nt * 8 + tg * 2;
                float r0 = 0.f, r1 = 0.f;
                if (c < CQ) {
                    r0 = fmaf(acc[mt][nt][half * 2 + 0], scale[c], bias[c]);
                    r1 = fmaf(acc[mt][nt][half * 2 + 1], scale[c + 1], bias[c + 1]);
                    r0 = r0 > 0.f ? r0 : 0.f;
                    r1 = r1 > 0.f ? r1 : 0.f;
                }
                __nv_bfloat162 pk;
                pk.x = __float2bfloat16(r0);
                pk.y = __float2bfloat16(r1);
                *(__nv_bfloat162*)&qT[(size_t)row * NP + c] = pk;
            }
        }
    }
}

__global__ __launch_bounds__(256)
void proj_v_kernel(const float* __restrict__ scale, const float* __restrict__ bias)
{
    extern __shared__ __align__(1024) char smem[];
    const uint32_t sb = smem_u32(smem);
    const int tid = threadIdx.x;
    const int lane = tid & 31, wid = tid >> 5;
    const int wm = wid >> 2, wn = wid & 3;
    const int bz = blockIdx.z, c0 = blockIdx.x * 128, n0 = blockIdx.y * 128;

    const uint4* Ag = (const uint4*)g_wv;
    const uint4* Bg = (const uint4*)(g_xT + (size_t)bz * NN * CC);

    float acc[4][4][4];
#pragma unroll
    for (int i = 0; i < 4; i++)
#pragma unroll
        for (int j = 0; j < 4; j++)
#pragma unroll
            for (int k = 0; k < 4; k++) acc[i][j][k] = 0.f;

    gemm128x128<8>(sb, Ag, Bg, CC / 8, CC / 8, c0, n0, acc);

    __nv_bfloat16* Yb = g_vb + (size_t)bz * CC * NN;
    const int g = lane >> 2, tg = lane & 3;
#pragma unroll
    for (int mt = 0; mt < 4; mt++) {
#pragma unroll
        for (int half = 0; half < 2; half++) {
            int c = c0 + wm * 64 + mt * 16 + g + half * 8;
            float s = scale[c], bi = bias[c];
#pragma unroll
            for (int nt = 0; nt < 4; nt++) {
                int n = n0 + wn * 32 + nt * 8 + tg * 2;
                float r0 = fmaf(acc[mt][nt][half * 2 + 0], s, bi);
                float r1 = fmaf(acc[mt][nt][half * 2 + 1], s, bi);
                __nv_bfloat162 pk;
                pk.x = __float2bfloat16(r0 > 0.f ? r0 : 0.f);
                pk.y = __float2bfloat16(r1 > 0.f ? r1 : 0.f);
                *(__nv_bfloat162*)&Yb[(size_t)c * NN + n] = pk;
            }
        }
    }
}

// ---------------------------------------------------------------------------
// FUSED energy+softmax v2: i-tile 64, j-chunk 64, 2 passes (128 iters).
// q frags preloaded in registers. smem ~57KB -> 2 CTAs/SM.
//   pass 1 (tt 0..63):   E = q_i · k_j^T, running row max
//   pass 2 (tt 64..127): recompute E, P = exp(E-m) -> bf16 g_attnb, row sums
// Warps: wm = wid>>1 (4 x 16 i), wn = wid&1 (2 x 32 j).
// smem: q 16K | k dbl 2x16K | P 8K | red 0.5K | m 0.25K
// ---------------------------------------------------------------------------
#define EQ   0
#define EK   16384
#define EP   49152
#define ERED 57344
#define EM   57856
#define ESMEM 58112

__global__ void __launch_bounds__(256, 2)
energy_softmax_kernel()
{
    extern __shared__ __align__(1024) char smem[];
    const uint32_t sb = smem_u32(smem);
    const int tid = threadIdx.x;
    const int lane = tid & 31, wid = tid >> 5;
    const int wm = wid >> 1, wn = wid & 1;
    const int g = lane >> 2, tg = lane & 3;
    const int bz = blockIdx.y, i0 = blockIdx.x * 64;

    const char* qg = (const char*)(g_qT + ((size_t)bz * NN + i0) * NP);
    const char* kg = (const char*)(g_kT + (size_t)bz * NN * NP);
    __nv_bfloat16* attn = g_attnb + (size_t)bz * NN * NN;

    float* red = (float*)(smem + ERED);   // [64][2]
    float* m_s = (float*)(smem + EM);     // [64]

    // prologue: q tile (group 1), k tile 0 (group 0 ordering via two commits)
    {
#pragma unroll
        for (int p = 0; p < 4; p++) {
            int idx = p * 256 + tid;
            int r = idx >> 4, c16 = idx & 15;
            CP_ASYNC16(sb + EQ + SW2(r, c16), qg + (size_t)r * 256 + c16 * 16);
        }
        CP_COMMIT();
#pragma unroll
        for (int p = 0; p < 4; p++) {
            int idx = p * 256 + tid;
            int r = idx >> 4, c16 = idx & 15;
            CP_ASYNC16(sb + EK + SW2(r, c16), kg + (size_t)r * 256 + c16 * 16);
        }
        CP_COMMIT();
    }
    CP_WAIT1();               // q ready
    __syncthreads();

    // preload q fragments (fixed for the whole kernel)
    const int a_row = wm * 16 + ((lane >> 3) & 1) * 8 + (lane & 7);
    const int a_kc = (lane >> 4) & 1;
    const int b_kc = (lane >> 3) & 1;
    uint32_t qf[8][4];
#pragma unroll
    for (int ks = 0; ks < 8; ks++)
        ldsm4(qf[ks][0], qf[ks][1], qf[ks][2], qf[ks][3], sb + EQ + SW2(a_row, ks * 2 + a_kc));

    int kb_r[2];
#pragma unroll
    for (int p = 0; p < 2; p++) kb_r[p] = wn * 32 + p * 16 + ((lane >> 4) & 1) * 8 + (lane & 7);

    float rm[2] = {-1e30f, -1e30f};   // running max rows g, g+8
    float rs[2] = {0.f, 0.f};

#pragma unroll 1
    for (int tt = 0; tt < 128; tt++) {
        // prefetch next k chunk
        if (tt + 1 < 128) {
            const int jn = (tt + 1) & 63;
            const uint32_t dK = sb + EK + ((tt + 1) & 1) * 16384;
            const char* src = kg + (size_t)jn * 64 * 256;
#pragma unroll
            for (int p = 0; p < 4; p++) {
                int idx = p * 256 + tid;
                int r = idx >> 4, c16 = idx & 15;
                CP_ASYNC16(dK + SW2(r, c16), src + (size_t)r * 256 + c16 * 16);
            }
            CP_COMMIT();
            CP_WAIT1();
        } else {
            CP_WAIT0();
        }

        if (tt == 64) {
            // finalize row max from pass 1
#pragma unroll
            for (int h = 0; h < 2; h++) {
                float v = rm[h];
                v = fmaxf(v, __shfl_xor_sync(0xffffffffu, v, 1));
                v = fmaxf(v, __shfl_xor_sync(0xffffffffu, v, 2));
                if (tg == 0) red[(wm * 16 + g + h * 8) * 2 + wn] = v;
            }
            __syncthreads();
            if (tid < 64) m_s[tid] = fmaxf(red[tid * 2], red[tid * 2 + 1]);
        }
        __syncthreads();   // k buffer visible (+ m_s visible at tt==64)

        const uint32_t Kb = sb + EK + (tt & 1) * 16384;

        // E gemm 64x64, K=128: per warp 16x32
        float acc[4][4];
#pragma unroll
        for (int nt = 0; nt < 4; nt++)
#pragma unroll
            for (int c = 0; c < 4; c++) acc[nt][c] = 0.f;
#pragma unroll
        for (int ks = 0; ks < 8; ks++) {
            uint32_t bF[2][4];
#pragma unroll
            for (int p = 0; p < 2; p++)
                ldsm4(bF[p][0], bF[p][1], bF[p][2], bF[p][3],
                      Kb + SW2(kb_r[p], ks * 2 + b_kc));
            mma16816(acc[0], qf[ks][0], qf[ks][1], qf[ks][2], qf[ks][3], bF[0][0], bF[0][1]);
            mma16816(acc[1], qf[ks][0], qf[ks][1], qf[ks][2], qf[ks][3], bF[0][2], bF[0][3]);
            mma16816(acc[2], qf[ks][0], qf[ks][1], qf[ks][2], qf[ks][3], bF[1][0], bF[1][1]);
            mma16816(acc[3], qf[ks][0], qf[ks][1], qf[ks][2], qf[ks][3], bF[1][2], bF[1][3]);
        }

        if (tt < 64) {
            // pass 1: running row max
#pragma unroll
            for (int nt = 0; nt < 4; nt++) {
                rm[0] = fmaxf(rm[0], fmaxf(acc[nt][0], acc[nt][1]));
                rm[1] = fmaxf(rm[1], fmaxf(acc[nt][2], acc[nt][3]));
            }
            __syncthreads();   // protect k buffer (WAR) before next prefetch
        } else {
            // pass 2: P = exp(E - m) -> smem bf16, accumulate row sums
            const int r0 = wm * 16 + g, r1 = r0 + 8;
            const float m0 = m_s[r0], m1 = m_s[r1];
#pragma unroll
            for (int nt = 0; nt < 4; nt++) {
                float p00 = __expf(acc[nt][0] - m0);
                float p01 = __expf(acc[nt][1] - m0);
                float p10 = __expf(acc[nt][2] - m1);
                float p11 = __expf(acc[nt][3] - m1);
                rs[0] += p00 + p01;
                rs[1] += p10 + p11;
                int jl = wn * 32 + nt * 8 + tg * 2;
                __nv_bfloat162 pk0 = __float22bfloat162_rn(make_float2(p00, p01));
                __nv_bfloat162 pk1 = __float22bfloat162_rn(make_float2(p10, p11));
                uint32_t a0 = sb + EP + r0 * 128 + (((jl >> 3) ^ (r0 & 7)) * 16) + ((jl * 2) & 15);
                uint32_t a1 = sb + EP + r1 * 128 + (((jl >> 3) ^ (r1 & 7)) * 16) + ((jl * 2) & 15);
                asm volatile("st.shared.b32 [%0], %1;" :: "r"(a0), "r"(*(uint32_t*)&pk0) : "memory");
                asm volatile("st.shared.b32 [%0], %1;" :: "r"(a1), "r"(*(uint32_t*)&pk1) : "memory");
            }
            __syncthreads();   // P tile complete + k buffer WAR protection
            // coalesced copy P (64x64 bf16 = 8KB) -> global
            const int jj = tt - 64;
#pragma unroll
            for (int p = 0; p < 2; p++) {
                int idx = p * 256 + tid;
                int r = idx >> 3, c8 = idx & 7;
                uint4 val = *(uint4*)(smem + EP + SW(r, c8));
                *(uint4*)&attn[(size_t)(i0 + r) * NN + jj * 64 + c8 * 8] = val;
            }
            __syncthreads();   // P smem WAR before next iteration's stores
        }
    }

    // finalize rowsum -> g_linv
#pragma unroll
    for (int h = 0; h < 2; h++) {
        float s = rs[h];
        s += __shfl_xor_sync(0xffffffffu, s, 1);
        s += __shfl_xor_sync(0xffffffffu, s, 2);
        if (tg == 0) red[(wm * 16 + g + h * 8) * 2 + wn] = s;
    }
    __syncthreads();
    if (tid < 64) {
        float l = red[tid * 2] + red[tid * 2 + 1];
        g_linv[(size_t)bz * NN + i0 + tid] = 1.f / l;
    }
}

// ---------------------------------------------------------------------------
// out: O[c,i] = (sum_j v[c,j]*P[i,j]) * linv[i];  out = gamma*O + x.
// ---------------------------------------------------------------------------
__global__ __launch_bounds__(256)
void out_kernel(const float* __restrict__ gamma, const float* __restrict__ x,
                float* __restrict__ out)
{
    extern __shared__ __align__(1024) char smem[];
    const uint32_t sb = smem_u32(smem);
    const int tid = threadIdx.x;
    const int lane = tid & 31, wid = tid >> 5;
    const int wm = wid >> 2, wn = wid & 3;
    const int bz = blockIdx.z, c0 = blockIdx.x * 128, i0 = blockIdx.y * 128;

    const uint4* va = (const uint4*)(g_vb    + (size_t)bz * CC * NN);
    const uint4* aa = (const uint4*)(g_attnb + (size_t)bz * NN * NN);

    float acc[4][4][4];
#pragma unroll
    for (int i = 0; i < 4; i++)
#pragma unroll
        for (int j = 0; j < 4; j++)
#pragma unroll
            for (int k = 0; k < 4; k++) acc[i][j][k] = 0.f;

    gemm128x128<64>(sb, va, aa, NN / 8, NN / 8, c0, i0, acc);

    const float* linv = g_linv + (size_t)bz * NN;
    const int g = lane >> 2, tg = lane & 3;

    float li[4][2];
#pragma unroll
    for (int nt = 0; nt < 4; nt++) {
        int n = i0 + wn * 32 + nt * 8 + tg * 2;
        li[nt][0] = linv[n];
        li[nt][1] = linv[n + 1];
    }

#pragma unroll
    for (int mt = 0; mt < 4; mt++) {
#pragma unroll
        for (int half = 0; half < 2; half++) {
            int c = c0 + wm * 64 + mt * 16 + g + half * 8;
#pragma unroll
            for (int nt = 0; nt < 4; nt++) {
                int n = i0 + wn * 32 + nt * 8 + tg * 2;
                size_t gi = (size_t)c * NN + n;
                size_t bi = (size_t)bz * CC * NN + gi;
                float2 gm = *(const float2*)&gamma[gi];
                float2 xx = *(const float2*)&x[bi];
                float2 o;
                o.x = fmaf(gm.x, acc[mt][nt][half * 2 + 0] * li[nt][0], xx.x);
                o.y = fmaf(gm.y, acc[mt][nt][half * 2 + 1] * li[nt][1], xx.y);
                *(float2*)&out[bi] = o;
            }
        }
    }
}

// ---------------------------------------------------------------------------
extern "C" void kernel_launch(void* const* d_in, const int* in_sizes, int n_in,
                              void* d_out, int out_size)
{
    const float* x     = (const float*)d_in[0];
    const float* Wq    = (const float*)d_in[1];
    const float* Wk    = (const float*)d_in[2];
    const float* Wv    = (const float*)d_in[3];
    const float* sq    = (const float*)d_in[4];
    const float* bq    = (const float*)d_in[5];
    const float* sk    = (const float*)d_in[6];
    const float* bk    = (const float*)d_in[7];
    const float* sv    = (const float*)d_in[8];
    const float* bv    = (const float*)d_in[9];
    const float* gamma = (const float*)d_in[10];
    float* out = (float*)d_out;

    const int DSMEM = 65536;
    cudaFuncSetAttribute(proj_qk_kernel, cudaFuncAttributeMaxDynamicSharedMemorySize, DSMEM);
    cudaFuncSetAttribute(proj_v_kernel,  cudaFuncAttributeMaxDynamicSharedMemorySize, DSMEM);
    cudaFuncSetAttribute(out_kernel,     cudaFuncAttributeMaxDynamicSharedMemorySize, DSMEM);
    cudaFuncSetAttribute(energy_softmax_kernel,
                         cudaFuncAttributeMaxDynamicSharedMemorySize, ESMEM);

    dim3 blk(256);

    convert_w_kernel<<<(CC * CC + 2 * NP * CC) / 256, blk>>>(Wv, Wq, Wk);
    transpose_x_kernel<<<dim3(CC / 128, NN / 128, BB), blk>>>(x);

    proj_qk_kernel<<<dim3(NN / 128, 1, BB), blk, DSMEM>>>(sq, bq, 0);
    proj_qk_kernel<<<dim3(NN / 128, 1, BB), blk, DSMEM>>>(sk, bk, 1);
    proj_v_kernel<<<dim3(CC / 128, NN / 128, BB), blk, DSMEM>>>(sv, bv);

    energy_softmax_kernel<<<dim3(NN / 64, BB), blk, ESMEM>>>();

    out_kernel<<<dim3(CC / 128, NN / 128, BB), blk, DSMEM>>>(gamma, x, out);
}

// round 8
// speedup vs baseline: 1.3677x; 1.1036x over previous
#include <cuda_runtime.h>
#include <cuda_bf16.h>
#include <cstdint>

#define BB 8
#define CC 512
#define NN 4096
#define CQ 80
#define NP 128   // CQ padded to 128 for bf16 MMA K

// ---------------- scratch (device globals; allocation-guard safe) ----------
__device__ __nv_bfloat16  g_attnb [(size_t)BB * NN * NN];   // 256 MB bf16 (unnormalized P)
__device__ float          g_lsum  [(size_t)BB * NN];        // row sums of P
__device__ float          g_qnorm [(size_t)BB * NN];        // ||q_i||_2
__device__ unsigned       g_kmax_bits[BB];                  // max_j ||k_j||_2 (float bits)
__device__ __nv_bfloat16  g_vb    [(size_t)BB * CC * NN];   // 64 MB  [b][c][n]
__device__ __nv_bfloat16  g_qT    [(size_t)BB * NN * NP];   // 8 MB   [b][n][c] padded
__device__ __nv_bfloat16  g_kT    [(size_t)BB * NN * NP];   // 8 MB
__device__ __nv_bfloat16  g_xT    [(size_t)BB * NN * CC];   // 33.5 MB [b][n][c]
__device__ __nv_bfloat16  g_wv    [(size_t)CC * CC];
__device__ __nv_bfloat16  g_wqp   [(size_t)NP * CC];
__device__ __nv_bfloat16  g_wkp   [(size_t)NP * CC];

// ---------------- helpers ---------------------------------------------------
__device__ __forceinline__ uint32_t smem_u32(const void* p) {
    uint32_t a;
    asm("{ .reg .u64 t; cvta.to.shared.u64 t, %1; cvt.u32.u64 %0, t; }" : "=r"(a) : "l"(p));
    return a;
}
__device__ __forceinline__ void ldsm4(uint32_t& r0, uint32_t& r1, uint32_t& r2, uint32_t& r3,
                                      uint32_t addr) {
    asm volatile("ldmatrix.sync.aligned.m8n8.x4.shared.b16 {%0,%1,%2,%3}, [%4];"
                 : "=r"(r0), "=r"(r1), "=r"(r2), "=r"(r3) : "r"(addr));
}
__device__ __forceinline__ void mma16816(float* c, uint32_t a0, uint32_t a1, uint32_t a2,
                                         uint32_t a3, uint32_t b0, uint32_t b1) {
    asm volatile("mma.sync.aligned.m16n8k16.row.col.f32.bf16.bf16.f32 "
                 "{%0,%1,%2,%3},{%4,%5,%6,%7},{%8,%9},{%0,%1,%2,%3};"
                 : "+f"(c[0]), "+f"(c[1]), "+f"(c[2]), "+f"(c[3])
                 : "r"(a0), "r"(a1), "r"(a2), "r"(a3), "r"(b0), "r"(b1));
}
#define CP_ASYNC16(dst, src) \
    asm volatile("cp.async.cg.shared.global [%0], [%1], 16;" :: "r"(dst), "l"(src))
#define CP_COMMIT() asm volatile("cp.async.commit_group;" ::: "memory")
#define CP_WAIT1()  asm volatile("cp.async.wait_group 1;" ::: "memory")
#define CP_WAIT0()  asm volatile("cp.async.wait_group 0;" ::: "memory")

// 128B-row (64 bf16) swizzle; chunk in [0,8)
#define SW(r, c) ((uint32_t)(((r) * 128) + ((((c) ^ ((r) & 7))) * 16)))

// ---------------------------------------------------------------------------
// 128x128 bf16 GEMM body.  C += A[128,K] * B[128,K]^T
// ---------------------------------------------------------------------------
template <int NK>
__device__ __forceinline__ void gemm128x128(uint32_t sb, const uint4* __restrict__ Ag,
                                            const uint4* __restrict__ Bg, int aStride,
                                            int bStride, int m0, int n0,
                                            float (&acc)[4][4][4]) {
    const int tid = threadIdx.x;
    const int lane = tid & 31, wid = tid >> 5;
    const int wm = wid >> 2, wn = wid & 3;
    const int lr = tid >> 3, lc = tid & 7;

    int a_r[4], b_r[2];
#pragma unroll
    for (int mt = 0; mt < 4; mt++) a_r[mt] = wm * 64 + mt * 16 + ((lane >> 3) & 1) * 8 + (lane & 7);
#pragma unroll
    for (int p = 0; p < 2; p++) b_r[p] = wn * 32 + p * 16 + ((lane >> 4) & 1) * 8 + (lane & 7);
    const int a_kc = (lane >> 4) & 1;
    const int b_kc = (lane >> 3) & 1;

    {
        uint32_t dA = sb, dB = sb + 16384;
#pragma unroll
        for (int p = 0; p < 4; p++) {
            int r = p * 32 + lr;
            CP_ASYNC16(dA + SW(r, lc), (const void*)(Ag + (size_t)(m0 + r) * aStride + lc));
            CP_ASYNC16(dB + SW(r, lc), (const void*)(Bg + (size_t)(n0 + r) * bStride + lc));
        }
        CP_COMMIT();
    }

#pragma unroll 1
    for (int t = 0; t < NK; t++) {
        if (t + 1 < NK) {
            uint32_t dA = sb + ((t + 1) & 1) * 32768, dB = dA + 16384;
#pragma unroll
            for (int p = 0; p < 4; p++) {
                int r = p * 32 + lr;
                CP_ASYNC16(dA + SW(r, lc),
                           (const void*)(Ag + (size_t)(m0 + r) * aStride + (t + 1) * 8 + lc));
                CP_ASYNC16(dB + SW(r, lc),
                           (const void*)(Bg + (size_t)(n0 + r) * bStride + (t + 1) * 8 + lc));
            }
            CP_COMMIT();
            CP_WAIT1();
        } else {
            CP_WAIT0();
        }
        __syncthreads();

        const uint32_t Asb = sb + (t & 1) * 32768;
        const uint32_t Bsb = Asb + 16384;
#pragma unroll
        for (int ks = 0; ks < 4; ks++) {
            uint32_t aF[4][4], bF[2][4];
#pragma unroll
            for (int mt = 0; mt < 4; mt++)
                ldsm4(aF[mt][0], aF[mt][1], aF[mt][2], aF[mt][3],
                      Asb + SW(a_r[mt], ks * 2 + a_kc));
#pragma unroll
            for (int p = 0; p < 2; p++)
                ldsm4(bF[p][0], bF[p][1], bF[p][2], bF[p][3],
                      Bsb + SW(b_r[p], ks * 2 + b_kc));
#pragma unroll
            for (int mt = 0; mt < 4; mt++) {
                mma16816(acc[mt][0], aF[mt][0], aF[mt][1], aF[mt][2], aF[mt][3], bF[0][0], bF[0][1]);
                mma16816(acc[mt][1], aF[mt][0], aF[mt][1], aF[mt][2], aF[mt][3], bF[0][2], bF[0][3]);
                mma16816(acc[mt][2], aF[mt][0], aF[mt][1], aF[mt][2], aF[mt][3], bF[1][0], bF[1][1]);
                mma16816(acc[mt][3], aF[mt][0], aF[mt][1], aF[mt][2], aF[mt][3], bF[1][2], bF[1][3]);
            }
        }
        __syncthreads();
    }
}

// ---------------------------------------------------------------------------
// convert_w (+ zero g_lsum / g_kmax_bits)
// ---------------------------------------------------------------------------
__global__ __launch_bounds__(256)
void convert_w_kernel(const float* __restrict__ Wv, const float* __restrict__ Wq,
                      const float* __restrict__ Wk)
{
    int idx = blockIdx.x * 256 + threadIdx.x;
    if (idx < BB * NN) g_lsum[idx] = 0.f;
    if (idx < BB) g_kmax_bits[idx] = 0u;
    if (idx < CC * CC) {
        g_wv[idx] = __float2bfloat16(Wv[idx]);
    } else if (idx < CC * CC + NP * CC) {
        int i = idx - CC * CC;
        int row = i >> 9, col = i & 511;
        g_wqp[i] = __float2bfloat16(row < CQ ? Wq[row * CC + col] : 0.f);
    } else {
        int i = idx - CC * CC - NP * CC;
        int row = i >> 9, col = i & 511;
        g_wkp[i] = __float2bfloat16(row < CQ ? Wk[row * CC + col] : 0.f);
    }
}

// ---------------------------------------------------------------------------
// transpose_x: x [b][c][n] fp32 -> xT [b][n][c] bf16.
// ---------------------------------------------------------------------------
__global__ __launch_bounds__(256)
void transpose_x_kernel(const float* __restrict__ x)
{
    __shared__ __nv_bfloat16 st[128][136];
    const int b  = blockIdx.z;
    const int c0 = blockIdx.x * 128;
    const int n0 = blockIdx.y * 128;
    const int tid = threadIdx.x;

    const float* xb = x + (size_t)b * CC * NN;
#pragma unroll
    for (int k = 0; k < 8; k++) {
        int row = k * 16 + (tid >> 4);
        int col = (tid & 15) * 8;
        const float* p = xb + (size_t)(c0 + row) * NN + n0 + col;
        float4 v0 = *(const float4*)p;
        float4 v1 = *(const float4*)(p + 4);
        st[col + 0][row] = __float2bfloat16(v0.x);
        st[col + 1][row] = __float2bfloat16(v0.y);
        st[col + 2][row] = __float2bfloat16(v0.z);
        st[col + 3][row] = __float2bfloat16(v0.w);
        st[col + 4][row] = __float2bfloat16(v1.x);
        st[col + 5][row] = __float2bfloat16(v1.y);
        st[col + 6][row] = __float2bfloat16(v1.z);
        st[col + 7][row] = __float2bfloat16(v1.w);
    }
    __syncthreads();

    uint4* xT = (uint4*)(g_xT + (size_t)b * NN * CC);
#pragma unroll
    for (int k = 0; k < 8; k++) {
        int idx = k * 256 + tid;
        int r = idx >> 4, j = idx & 15;
        uint4 val = *(uint4*)&st[r][j * 8];
        xT[(size_t)(n0 + r) * (CC / 8) + (c0 >> 3) + j] = val;
    }
}

// ---------------------------------------------------------------------------
// proj_qk / proj_v (unchanged, working)
// ---------------------------------------------------------------------------
__global__ __launch_bounds__(256)
void proj_qk_kernel(const float* __restrict__ scale, const float* __restrict__ bias,
                    int which)
{
    extern __shared__ __align__(1024) char smem[];
    const uint32_t sb = smem_u32(smem);
    const int tid = threadIdx.x;
    const int lane = tid & 31, wid = tid >> 5;
    const int wm = wid >> 2, wn = wid & 3;
    const int bz = blockIdx.z, n0 = blockIdx.x * 128;

    const uint4* Ag = (const uint4*)(g_xT + (size_t)bz * NN * CC);
    const uint4* Bg = (const uint4*)(which ? g_wkp : g_wqp);

    float acc[4][4][4];
#pragma unroll
    for (int i = 0; i < 4; i++)
#pragma unroll
        for (int j = 0; j < 4; j++)
#pragma unroll
            for (int k = 0; k < 4; k++) acc[i][j][k] = 0.f;

    gemm128x128<8>(sb, Ag, Bg, CC / 8, CC / 8, n0, 0, acc);

    __nv_bfloat16* qT = (which ? g_kT : g_qT) + (size_t)bz * NN * NP;
    const int g = lane >> 2, tg = lane & 3;
#pragma unroll
    for (int mt = 0; mt < 4; mt++) {
#pragma unroll
        for (int half = 0; half < 2; half++) {
            int row = n0 + wm * 64 + mt * 16 + g + half * 8;
#pragma unroll
            for (int nt = 0; nt < 4; nt++) {
                int c = wn * 32 + nt * 8 + tg * 2;
                float r0 = 0.f, r1 = 0.f;
                if (c < CQ) {
                    r0 = fmaf(acc[mt][nt][half * 2 + 0], scale[c], bias[c]);
                    r1 = fmaf(acc[mt][nt][half * 2 + 1], scale[c + 1], bias[c + 1]);
                    r0 = r0 > 0.f ? r0 : 0.f;
                    r1 = r1 > 0.f ? r1 : 0.f;
                }
                __nv_bfloat162 pk;
                pk.x = __float2bfloat16(r0);
                pk.y = __float2bfloat16(r1);
                *(__nv_bfloat162*)&qT[(size_t)row * NP + c] = pk;
            }
        }
    }
}

__global__ __launch_bounds__(256)
void proj_v_kernel(const float* __restrict__ scale, const float* __restrict__ bias)
{
    extern __shared__ __align__(1024) char smem[];
    const uint32_t sb = smem_u32(smem);
    const int tid = threadIdx.x;
    const int lane = tid & 31, wid = tid >> 5;
    const int wm = wid >> 2, wn = wid & 3;
    const int bz = blockIdx.z, c0 = blockIdx.x * 128, n0 = blockIdx.y * 128;

    const uint4* Ag = (const uint4*)g_wv;
    const uint4* Bg = (const uint4*)(g_xT + (size_t)bz * NN * CC);

    float acc[4][4][4];
#pragma unroll
    for (int i = 0; i < 4; i++)
#pragma unroll
        for (int j = 0; j < 4; j++)
#pragma unroll
            for (int k = 0; k < 4; k++) acc[i][j][k] = 0.f;

    gemm128x128<8>(sb, Ag, Bg, CC / 8, CC / 8, c0, n0, acc);

    __nv_bfloat16* Yb = g_vb + (size_t)bz * CC * NN;
    const int g = lane >> 2, tg = lane & 3;
#pragma unroll
    for (int mt = 0; mt < 4; mt++) {
#pragma unroll
        for (int half = 0; half < 2; half++) {
            int c = c0 + wm * 64 + mt * 16 + g + half * 8;
            float s = scale[c], bi = bias[c];
#pragma unroll
            for (int nt = 0; nt < 4; nt++) {
                int n = n0 + wn * 32 + nt * 8 + tg * 2;
                float r0 = fmaf(acc[mt][nt][half * 2 + 0], s, bi);
                float r1 = fmaf(acc[mt][nt][half * 2 + 1], s, bi);
                __nv_bfloat162 pk;
                pk.x = __float2bfloat16(r0 > 0.f ? r0 : 0.f);
                pk.y = __float2bfloat16(r1 > 0.f ? r1 : 0.f);
                *(__nv_bfloat162*)&Yb[(size_t)c * NN + n] = pk;
            }
        }
    }
}

// ---------------------------------------------------------------------------
// qk_norms: ||q_i||2 per row -> g_qnorm; atomicMax ||k_j||2 per batch.
// One thread per row. grid BB*NN/256.
// ---------------------------------------------------------------------------
__global__ __launch_bounds__(256)
void qk_norms_kernel()
{
    const int row = blockIdx.x * 256 + threadIdx.x;   // 0 .. BB*NN-1
    const int b = row >> 12;

    const uint4* qr = (const uint4*)(g_qT + (size_t)row * NP);
    const uint4* kr = (const uint4*)(g_kT + (size_t)row * NP);
    float qs = 0.f, ks = 0.f;
#pragma unroll
    for (int j = 0; j < 16; j++) {
        uint4 qv = qr[j], kv = kr[j];
        const uint32_t* qw = (const uint32_t*)&qv;
        const uint32_t* kw = (const uint32_t*)&kv;
#pragma unroll
        for (int w = 0; w < 4; w++) {
            float2 qf = __bfloat1622float2(*(const __nv_bfloat162*)&qw[w]);
            float2 kf = __bfloat1622float2(*(const __nv_bfloat162*)&kw[w]);
            qs = fmaf(qf.x, qf.x, qs); qs = fmaf(qf.y, qf.y, qs);
            ks = fmaf(kf.x, kf.x, ks); ks = fmaf(kf.y, kf.y, ks);
        }
    }
    g_qnorm[row] = sqrtf(qs);
    float kn = sqrtf(ks);
    atomicMax(&g_kmax_bits[b], __float_as_uint(kn));  // kn >= 0: uint order == float order
}

// ---------------------------------------------------------------------------
// energy_p: single pass. P[i,j] = exp(q_i·k_j - bound_i) -> bf16 g_attnb,
// partial row sums atomicAdd into g_lsum. bound_i = ||q_i|| * max||k||.
// Softmax invariance to per-row constants makes this exact; E>=0 and
// bound <= ~15 rule out under/overflow.
// ---------------------------------------------------------------------------
__global__ __launch_bounds__(256)
void energy_p_kernel()
{
    extern __shared__ __align__(1024) char smem[];
    const uint32_t sb = smem_u32(smem);
    const int tid = threadIdx.x;
    const int lane = tid & 31, wid = tid >> 5;
    const int wm = wid >> 2, wn = wid & 3;
    const int bz = blockIdx.z, i0 = blockIdx.x * 128, j0 = blockIdx.y * 128;

    const uint4* qa = (const uint4*)(g_qT + (size_t)bz * NN * NP);
    const uint4* ka = (const uint4*)(g_kT + (size_t)bz * NN * NP);

    float acc[4][4][4];
#pragma unroll
    for (int i = 0; i < 4; i++)
#pragma unroll
        for (int j = 0; j < 4; j++)
#pragma unroll
            for (int k = 0; k < 4; k++) acc[i][j][k] = 0.f;

    gemm128x128<2>(sb, qa, ka, NP / 8, NP / 8, i0, j0, acc);

    const float kmax = __uint_as_float(g_kmax_bits[bz]);
    const float* qn = g_qnorm + (size_t)bz * NN;
    float* lsum = g_lsum + (size_t)bz * NN;
    __nv_bfloat16* attn = g_attnb + (size_t)bz * NN * NN;

    const int g = lane >> 2, tg = lane & 3;
#pragma unroll
    for (int mt = 0; mt < 4; mt++) {
        const int m0r = i0 + wm * 64 + mt * 16 + g;
        const float b0 = qn[m0r] * kmax;
        const float b1 = qn[m0r + 8] * kmax;
        float s0 = 0.f, s1 = 0.f;
#pragma unroll
        for (int nt = 0; nt < 4; nt++) {
            int n = j0 + wn * 32 + nt * 8 + tg * 2;
            float p00 = __expf(acc[mt][nt][0] - b0);
            float p01 = __expf(acc[mt][nt][1] - b0);
            float p10 = __expf(acc[mt][nt][2] - b1);
            float p11 = __expf(acc[mt][nt][3] - b1);
            s0 += p00 + p01;
            s1 += p10 + p11;
            __nv_bfloat162 pk0 = __float22bfloat162_rn(make_float2(p00, p01));
            __nv_bfloat162 pk1 = __float22bfloat162_rn(make_float2(p10, p11));
            *(__nv_bfloat162*)&attn[(size_t)m0r * NN + n]       = pk0;
            *(__nv_bfloat162*)&attn[(size_t)(m0r + 8) * NN + n] = pk1;
        }
        // reduce over tg lanes (same row), one atomic per row-fragment
        s0 += __shfl_xor_sync(0xffffffffu, s0, 1);
        s0 += __shfl_xor_sync(0xffffffffu, s0, 2);
        s1 += __shfl_xor_sync(0xffffffffu, s1, 1);
        s1 += __shfl_xor_sync(0xffffffffu, s1, 2);
        if (tg == 0) {
            atomicAdd(&lsum[m0r], s0);
            atomicAdd(&lsum[m0r + 8], s1);
        }
    }
}

// ---------------------------------------------------------------------------
// out: O[c,i] = (sum_j v[c,j]*P[i,j]) / lsum[i];  out = gamma*O + x.
// ---------------------------------------------------------------------------
__global__ __launch_bounds__(256)
void out_kernel(const float* __restrict__ gamma, const float* __restrict__ x,
                float* __restrict__ out)
{
    extern __shared__ __align__(1024) char smem[];
    const uint32_t sb = smem_u32(smem);
    const int tid = threadIdx.x;
    const int lane = tid & 31, wid = tid >> 5;
    const int wm = wid >> 2, wn = wid & 3;
    const int bz = blockIdx.z, c0 = blockIdx.x * 128, i0 = blockIdx.y * 128;

    const uint4* va = (const uint4*)(g_vb    + (size_t)bz * CC * NN);
    const uint4* aa = (const uint4*)(g_attnb + (size_t)bz * NN * NN);

    float acc[4][4][4];
#pragma unroll
    for (int i = 0; i < 4; i++)
#pragma unroll
        for (int j = 0; j < 4; j++)
#pragma unroll
            for (int k = 0; k < 4; k++) acc[i][j][k] = 0.f;

    gemm128x128<64>(sb, va, aa, NN / 8, NN / 8, c0, i0, acc);

    const float* lsum = g_lsum + (size_t)bz * NN;
    const int g = lane >> 2, tg = lane & 3;

    float li[4][2];
#pragma unroll
    for (int nt = 0; nt < 4; nt++) {
        int n = i0 + wn * 32 + nt * 8 + tg * 2;
        li[nt][0] = 1.f / lsum[n];
        li[nt][1] = 1.f / lsum[n + 1];
    }

#pragma unroll
    for (int mt = 0; mt < 4; mt++) {
#pragma unroll
        for (int half = 0; half < 2; half++) {
            int c = c0 + wm * 64 + mt * 16 + g + half * 8;
#pragma unroll
            for (int nt = 0; nt < 4; nt++) {
                int n = i0 + wn * 32 + nt * 8 + tg * 2;
                size_t gi = (size_t)c * NN + n;
                size_t bi = (size_t)bz * CC * NN + gi;
                float2 gm = *(const float2*)&gamma[gi];
                float2 xx = *(const float2*)&x[bi];
                float2 o;
                o.x = fmaf(gm.x, acc[mt][nt][half * 2 + 0] * li[nt][0], xx.x);
                o.y = fmaf(gm.y, acc[mt][nt][half * 2 + 1] * li[nt][1], xx.y);
                *(float2*)&out[bi] = o;
            }
        }
    }
}

// ---------------------------------------------------------------------------
extern "C" void kernel_launch(void* const* d_in, const int* in_sizes, int n_in,
                              void* d_out, int out_size)
{
    const float* x     = (const float*)d_in[0];
    const float* Wq    = (const float*)d_in[1];
    const float* Wk    = (const float*)d_in[2];
    const float* Wv    = (const float*)d_in[3];
    const float* sq    = (const float*)d_in[4];
    const float* bq    = (const float*)d_in[5];
    const float* sk    = (const float*)d_in[6];
    const float* bk    = (const float*)d_in[7];
    const float* sv    = (const float*)d_in[8];
    const float* bv    = (const float*)d_in[9];
    const float* gamma = (const float*)d_in[10];
    float* out = (float*)d_out;

    const int DSMEM = 65536;
    cudaFuncSetAttribute(proj_qk_kernel, cudaFuncAttributeMaxDynamicSharedMemorySize, DSMEM);
    cudaFuncSetAttribute(proj_v_kernel,  cudaFuncAttributeMaxDynamicSharedMemorySize, DSMEM);
    cudaFuncSetAttribute(energy_p_kernel, cudaFuncAttributeMaxDynamicSharedMemorySize, DSMEM);
    cudaFuncSetAttribute(out_kernel,     cudaFuncAttributeMaxDynamicSharedMemorySize, DSMEM);

    dim3 blk(256);

    convert_w_kernel<<<(CC * CC + 2 * NP * CC) / 256, blk>>>(Wv, Wq, Wk);
    transpose_x_kernel<<<dim3(CC / 128, NN / 128, BB), blk>>>(x);

    proj_qk_kernel<<<dim3(NN / 128, 1, BB), blk, DSMEM>>>(sq, bq, 0);
    proj_qk_kernel<<<dim3(NN / 128, 1, BB), blk, DSMEM>>>(sk, bk, 1);

    qk_norms_kernel<<<BB * NN / 256, blk>>>();

    proj_v_kernel<<<dim3(CC / 128, NN / 128, BB), blk, DSMEM>>>(sv, bv);

    energy_p_kernel<<<dim3(NN / 128, NN / 128, BB), blk, DSMEM>>>();

    out_kernel<<<dim3(CC / 128, NN / 128, BB), blk, DSMEM>>>(gamma, x, out);
}